// round 16
// baseline (speedup 1.0000x reference)
#include <cuda_runtime.h>
#include <cuda_fp16.h>
#include <math.h>

#define N 4096
#define LOG16   2.772588722239781f    // log(16)
#define LOG_CU  13.862943611198906f   // log(2^20)
#define F_SCALE 1048576.0f            // 2^20
#define NBLOCKS 256
#define NTHREADS 256
#define NITER 10
#define NTILES 256                    // k-tiles per row (N/16)
#define TPW 32                        // tiles per warp (256/8)

// Scratch (allocation-free rule: __device__ globals).
// K matrices FRAGMENT-MAJOR: tile t = rt*256+kt occupies 32 uint4; lane l's
// uint4 at t*32+l = {a0..a3} of mma.m16n8k16. B vectors FRAGMENT-PACKED:
// tile t occupies 16 uint2 (lanes 0-15 only; n>=4 rows are implicit zeros).
__device__ __half    g_K [(size_t)N * N];
__device__ __half    g_KT[(size_t)N * N];
__device__ uint2     g_Bv[NTILES * 16];   // packed v (input of even passes)
__device__ uint2     g_Bu[NTILES * 16];   // packed u (input of odd passes)
__device__ float     g_pu[N * 4];         // final Kv sums  [row][s]
__device__ float     g_pv[N * 4];         // final KTu sums [row][s]
__device__ unsigned  g_gc[8 * 32];        // 8 group counters, 128B apart (monotonic)
__device__ unsigned long long g_count;    // grid-barrier generation counter

// ---------------------------------------------------------------------------
// Software grid barrier (used only twice: post-init, pre-finalize)
// ---------------------------------------------------------------------------
__device__ __forceinline__ void grid_sync() {
    __syncthreads();
    if (threadIdx.x == 0) {
        unsigned long long gen;
        asm volatile("atom.add.release.gpu.u64 %0, [%1], 1;"
                     : "=l"(gen) : "l"(&g_count) : "memory");
        unsigned long long target =
            (gen / NBLOCKS + 1ull) * (unsigned long long)NBLOCKS;
        unsigned long long cur;
        do {
            asm volatile("ld.acquire.gpu.u64 %0, [%1];"
                         : "=l"(cur) : "l"(&g_count) : "memory");
        } while (cur < target);
    }
    __syncthreads();
}

__device__ __forceinline__ unsigned packh(__half lo, __half hi) {
    __half2 h = __halves2half2(lo, hi);
    return *reinterpret_cast<unsigned*>(&h);
}

// Group wait: all 32 lanes load the SAME counter address (1 coalesced L2
// request per poll). Fast first check, then nanosleep backoff.
__device__ __forceinline__ void wait_group(const unsigned* cnt, unsigned tgt) {
    unsigned c;
    asm volatile("ld.acquire.gpu.b32 %0, [%1];" : "=r"(c) : "l"(cnt));
    while (c < tgt) {
        __nanosleep(200);
        asm volatile("ld.acquire.gpu.b32 %0, [%1];" : "=r"(c) : "l"(cnt));
    }
}

// ---------------------------------------------------------------------------
// Fragment packer: 64x64 C region -> exp -> 16 K-tiles + 16 KT-tiles,
// written directly in m16n8k16 A-fragment layout (uint4 per lane).
// ---------------------------------------------------------------------------
__global__ void frag_pack_kernel(const float* __restrict__ C,
                                 const float* __restrict__ epsp) {
    __shared__ __half sE[64 * 72];           // padded stride 72
    const float inv_eps = 1.0f / *epsp;
    const int tid = threadIdx.x;
    const int bx = blockIdx.x << 6;          // C column base
    const int by = blockIdx.y << 6;          // C row base

    {
        const int r  = tid >> 2;
        const int c0 = (tid & 3) << 4;
        const float4* src = (const float4*)(C + (size_t)(by + r) * N + bx + c0);
        __half* dst = sE + r * 72 + c0;
#pragma unroll
        for (int q = 0; q < 4; ++q) {
            float4 f = src[q];
            dst[q * 4 + 0] = __float2half_rn(__expf(LOG16 - f.x * inv_eps));
            dst[q * 4 + 1] = __float2half_rn(__expf(LOG16 - f.y * inv_eps));
            dst[q * 4 + 2] = __float2half_rn(__expf(LOG16 - f.z * inv_eps));
            dst[q * 4 + 3] = __float2half_rn(__expf(LOG16 - f.w * inv_eps));
        }
    }
    __syncthreads();

    const int warp = tid >> 5, lane = tid & 31;
    const int rr = lane >> 2, cc = (lane & 3) << 1;

#pragma unroll
    for (int p = 0; p < 2; ++p) {
        const int t = warp * 2 + p;          // 0..15
        const int i = t >> 2, j = t & 3;

        {   // K tile: rows = C rows, k = C cols
            const __half* b = sE + (i * 16 + rr) * 72 + (j * 16 + cc);
            unsigned r0 = *(const unsigned*)(b);
            unsigned r1 = *(const unsigned*)(b + 8 * 72);
            unsigned r2 = *(const unsigned*)(b + 8);
            unsigned r3 = *(const unsigned*)(b + 8 * 72 + 8);
            size_t tileK = ((size_t)((by >> 4) + i) * NTILES) + (bx >> 4) + j;
            ((uint4*)g_K)[tileK * 32 + lane] = make_uint4(r0, r1, r2, r3);
        }
        {   // KT tile: rows = C cols, k = C rows (transposed read)
            const __half* b = sE + (j * 16 + cc) * 72 + (i * 16 + rr);
            unsigned r0 = packh(b[0],          b[72]);
            unsigned r1 = packh(b[8],          b[72 + 8]);
            unsigned r2 = packh(b[8 * 72],     b[9 * 72]);
            unsigned r3 = packh(b[8 * 72 + 8], b[9 * 72 + 8]);
            size_t tileT = ((size_t)((bx >> 4) + i) * NTILES) + (by >> 4) + j;
            ((uint4*)g_KT)[tileT * 32 + lane] = make_uint4(r0, r1, r2, r3);
        }
    }
}

// ---------------------------------------------------------------------------
// Persistent tensor-core Sinkhorn (R14) + numerator prefetch + early publish.
// 256 blocks x 256 threads. Block rt = 16 rows x FULL 4096 cols; warp w
// covers k-tiles [32w, 32w+32) = B tiles produced by group w.
// ---------------------------------------------------------------------------
__global__ void __launch_bounds__(NTHREADS, 2)
sinkhorn_persistent_kernel(const float* __restrict__ alpha,
                           const float* __restrict__ beta,
                           const float* __restrict__ epsp,
                           float* __restrict__ out) {
    __shared__ float    red[8 * 16 * 4];
    __shared__ __half   yb[16 * 4];
    __shared__ unsigned sbase[8];

    const int tid  = threadIdx.x;
    const int warp = tid >> 5;
    const int lane = tid & 31;
    const int rt   = blockIdx.x;
    const int row0 = rt * 16;
    const bool bl  = lane < 16;

    const unsigned* mycnt  = g_gc + warp * 32;      // group this warp consumes
    unsigned*       arrcnt = g_gc + (rt >> 5) * 32; // group this block produces

    // read launch-base counter values BEFORE any arrival, then fence grid-wide
    if (tid < 8) {
        unsigned c;
        asm volatile("ld.relaxed.gpu.b32 %0, [%1];" : "=r"(c) : "l"(g_gc + tid * 32));
        sbase[tid] = c;
    }
    grid_sync();   // all base reads done; packer output visible

    const unsigned base = sbase[warp];

    // init packed v = 1.0 (tile rt), publish as generation 1
    if (warp == 0 && bl)
        __stcg(&g_Bv[rt * 16 + lane], make_uint2(0x3C003C00u, 0x3C003C00u));
    __syncthreads();
    if (tid == 0) {
        unsigned dummy;
        asm volatile("atom.add.release.gpu.u32 %0, [%1], 1;"
                     : "=r"(dummy) : "l"(arrcnt) : "memory");
    }

    const size_t fbase = ((size_t)rt * NTILES + warp * TPW) * 32 + lane;

    for (int it = 0; it < 2 * NITER; ++it) {
        const __half* M    = (it & 1) ? g_KT : g_K;
        const uint2*  Bin  = (it & 1) ? g_Bu : g_Bv;
        uint2*        Bout = (it & 1) ? g_Bv : g_Bu;
        float*        pdst = (it & 1) ? g_pv : g_pu;
        const float*  num  = (it & 1) ? beta : alpha;

        const uint4* kf = (const uint4*)M + fbase;
        const uint2* bf = Bin + (warp * TPW) * 16 + lane;

        // numerator prefetch: independent of producers, hides epilogue LDG
        float mynum = 0.f;
        if (tid < 64)
            mynum = __ldg(num + (size_t)(tid & 3) * N + row0 + (tid >> 2));

        float dA0 = 0.f, dA1 = 0.f, dA2 = 0.f, dA3 = 0.f;
        float dB0 = 0.f, dB1 = 0.f, dB2 = 0.f, dB3 = 0.f;

        uint4 ka[4];
        uint2 ba[4];
        // K prologue loads do NOT depend on producers: issue before the wait
#pragma unroll
        for (int q = 0; q < 4; ++q) ka[q] = __ldcg(kf + q * 32);

        // dataflow wait: group w must have published generation it+1
        wait_group(mycnt, base + (unsigned)(it + 1) * 32);

#pragma unroll
        for (int q = 0; q < 4; ++q)
            ba[q] = bl ? __ldcg(bf + q * 16) : make_uint2(0u, 0u);

#pragma unroll
        for (int g = 0; g < TPW / 4; ++g) {      // 8 groups of 4 tiles
            uint4 nk[4];
            uint2 nb[4];
#pragma unroll
            for (int q = 0; q < 4; ++q) {
                if (g < TPW / 4 - 1) {
                    nk[q] = __ldcg(kf + ((g + 1) * 4 + q) * 32);
                    nb[q] = bl ? __ldcg(bf + ((g + 1) * 4 + q) * 16) : make_uint2(0u, 0u);
                } else { nk[q] = ka[q]; nb[q] = ba[q]; }
            }
#pragma unroll
            for (int q = 0; q < 4; ++q) {
                if (q & 1) {
                    asm volatile("mma.sync.aligned.m16n8k16.row.col.f32.f16.f16.f32 "
                                 "{%0,%1,%2,%3}, {%4,%5,%6,%7}, {%8,%9}, {%0,%1,%2,%3};"
                                 : "+f"(dB0), "+f"(dB1), "+f"(dB2), "+f"(dB3)
                                 : "r"(ka[q].x), "r"(ka[q].y), "r"(ka[q].z), "r"(ka[q].w),
                                   "r"(ba[q].x), "r"(ba[q].y));
                } else {
                    asm volatile("mma.sync.aligned.m16n8k16.row.col.f32.f16.f16.f32 "
                                 "{%0,%1,%2,%3}, {%4,%5,%6,%7}, {%8,%9}, {%0,%1,%2,%3};"
                                 : "+f"(dA0), "+f"(dA1), "+f"(dA2), "+f"(dA3)
                                 : "r"(ka[q].x), "r"(ka[q].y), "r"(ka[q].z), "r"(ka[q].w),
                                   "r"(ba[q].x), "r"(ba[q].y));
                }
            }
#pragma unroll
            for (int q = 0; q < 4; ++q) { ka[q] = nk[q]; ba[q] = nb[q]; }
        }

        const float d0 = dA0 + dB0, d1 = dA1 + dB1;
        const float d2 = dA2 + dB2, d3 = dA3 + dB3;

        // ---- epilogue: C fragments (cols 0-3 useful) -> smem -> reduce ----
        if ((lane & 3) < 2) {
            const int c = 2 * (lane & 3);
            const int r = lane >> 2;
            red[(warp * 16 + r) * 4 + c]         = d0;
            red[(warp * 16 + r) * 4 + c + 1]     = d1;
            red[(warp * 16 + r + 8) * 4 + c]     = d2;
            red[(warp * 16 + r + 8) * 4 + c + 1] = d3;
        }
        __syncthreads();
        if (tid < 64) {
            const int row = tid >> 2, c = tid & 3;
            float p = 0.f;
#pragma unroll
            for (int w = 0; w < 8; ++w)
                p += red[(w * 16 + row) * 4 + c];
            if (it >= 2 * NITER - 2)
                __stcg(pdst + (size_t)(row0 + row) * 4 + c, p);
            float y = __fdividef(F_SCALE * mynum, p);
            yb[row * 4 + c] = __float2half_rn(y);
        }
        __syncthreads();
        // warp 0: pack tile rt of next B operand, then EARLY publish.
        // (yb/red reuse in pass it+1 is gated by that pass's first
        //  __syncthreads, which warp 0 must join — others may run ahead.)
        if (warp == 0) {
            if (bl) {
                const int n = lane >> 2, k0 = (lane & 3) * 2;
                uint2 o;
                o.x = packh(yb[k0 * 4 + n],       yb[(k0 + 1) * 4 + n]);
                o.y = packh(yb[(k0 + 8) * 4 + n], yb[(k0 + 9) * 4 + n]);
                __stcg(&Bout[rt * 16 + lane], o);
            }
            __syncwarp();
            if (lane == 0) {
                __threadfence();
                unsigned dummy;
                asm volatile("atom.add.release.gpu.u32 %0, [%1], 1;"
                             : "=r"(dummy) : "l"(arrcnt) : "memory");
            }
        }
    }

    grid_sync();   // g_pu/g_pv visible for cross-block finalize reads

    // ---- finalize:  f = eps*(log a - log p_u + log16)
    //                 g = eps*(log b - log p_v + log 2^20)
    int n = blockIdx.x * NTHREADS + tid;
    if (n < N) {
        const float eps = *epsp;
        float4 pu = __ldcg((const float4*)g_pu + n);
        float4 pv = __ldcg((const float4*)g_pv + n);
        out[0 * N + n] = eps * (logf(alpha[0 * N + n]) - logf(pu.x) + LOG16);
        out[1 * N + n] = eps * (logf(alpha[1 * N + n]) - logf(pu.y) + LOG16);
        out[2 * N + n] = eps * (logf(alpha[2 * N + n]) - logf(pu.z) + LOG16);
        out[3 * N + n] = eps * (logf(alpha[3 * N + n]) - logf(pu.w) + LOG16);
        float* og = out + 4 * N;
        og[0 * N + n] = eps * (logf(beta[0 * N + n]) - logf(pv.x) + LOG_CU);
        og[1 * N + n] = eps * (logf(beta[1 * N + n]) - logf(pv.y) + LOG_CU);
        og[2 * N + n] = eps * (logf(beta[2 * N + n]) - logf(pv.z) + LOG_CU);
        og[3 * N + n] = eps * (logf(beta[3 * N + n]) - logf(pv.w) + LOG_CU);
    }
}

// ---------------------------------------------------------------------------
extern "C" void kernel_launch(void* const* d_in, const int* in_sizes, int n_in,
                              void* d_out, int out_size) {
    const float* alpha = (const float*)d_in[0];
    const float* beta  = (const float*)d_in[1];
    const float* C     = (const float*)d_in[2];
    const float* eps   = (const float*)d_in[3];
    float* out = (float*)d_out;

    frag_pack_kernel<<<dim3(64, 64), 256>>>(C, eps);
    sinkhorn_persistent_kernel<<<NBLOCKS, NTHREADS>>>(alpha, beta, eps, out);
}

// round 17
// speedup vs baseline: 1.1562x; 1.1562x over previous
#include <cuda_runtime.h>
#include <cuda_fp16.h>
#include <math.h>

#define N 4096
#define LOG16   2.772588722239781f    // log(16)
#define LOG_CU  13.862943611198906f   // log(2^20)
#define F_SCALE 1048576.0f            // 2^20
#define NBLOCKS 256
#define NTHREADS 256
#define NITER 10
#define NTILES 256                    // k-tiles per row (N/16)
#define TPW 32                        // tiles per warp (256/8)

// Scratch (allocation-free rule: __device__ globals).
// K matrices FRAGMENT-MAJOR: tile t = rt*256+kt occupies 32 uint4; lane l's
// uint4 at t*32+l = {a0..a3} of mma.m16n8k16. B vectors FRAGMENT-PACKED:
// tile t occupies 16 uint2 (lanes 0-15 only; n>=4 rows are implicit zeros).
__device__ __half    g_K [(size_t)N * N];
__device__ __half    g_KT[(size_t)N * N];
__device__ uint2     g_Bv[NTILES * 16];   // packed v (input of even passes)
__device__ uint2     g_Bu[NTILES * 16];   // packed u (input of odd passes)
__device__ unsigned  g_gc[8 * 32];        // 8 group counters, 128B apart (monotonic)
__device__ unsigned long long g_count;    // grid-barrier generation counter

// ---------------------------------------------------------------------------
// Software grid barrier (used only once: post-init fence)
// ---------------------------------------------------------------------------
__device__ __forceinline__ void grid_sync() {
    __syncthreads();
    if (threadIdx.x == 0) {
        unsigned long long gen;
        asm volatile("atom.add.release.gpu.u64 %0, [%1], 1;"
                     : "=l"(gen) : "l"(&g_count) : "memory");
        unsigned long long target =
            (gen / NBLOCKS + 1ull) * (unsigned long long)NBLOCKS;
        unsigned long long cur;
        do {
            asm volatile("ld.acquire.gpu.u64 %0, [%1];"
                         : "=l"(cur) : "l"(&g_count) : "memory");
        } while (cur < target);
    }
    __syncthreads();
}

__device__ __forceinline__ unsigned packh(__half lo, __half hi) {
    __half2 h = __halves2half2(lo, hi);
    return *reinterpret_cast<unsigned*>(&h);
}

// Group wait: all 32 lanes load the SAME counter address (1 coalesced L2
// request per poll). Fast first check, then nanosleep backoff.
__device__ __forceinline__ void wait_group(const unsigned* cnt, unsigned tgt) {
    unsigned c;
    asm volatile("ld.acquire.gpu.b32 %0, [%1];" : "=r"(c) : "l"(cnt));
    while (c < tgt) {
        __nanosleep(200);
        asm volatile("ld.acquire.gpu.b32 %0, [%1];" : "=r"(c) : "l"(cnt));
    }
}

// ---------------------------------------------------------------------------
// Fragment packer: 64x64 C region -> exp -> 16 K-tiles + 16 KT-tiles,
// written directly in m16n8k16 A-fragment layout (uint4 per lane).
// ---------------------------------------------------------------------------
__global__ void frag_pack_kernel(const float* __restrict__ C,
                                 const float* __restrict__ epsp) {
    __shared__ __half sE[64 * 72];           // padded stride 72
    const float inv_eps = 1.0f / *epsp;
    const int tid = threadIdx.x;
    const int bx = blockIdx.x << 6;          // C column base
    const int by = blockIdx.y << 6;          // C row base

    {
        const int r  = tid >> 2;
        const int c0 = (tid & 3) << 4;
        const float4* src = (const float4*)(C + (size_t)(by + r) * N + bx + c0);
        __half* dst = sE + r * 72 + c0;
#pragma unroll
        for (int q = 0; q < 4; ++q) {
            float4 f = src[q];
            dst[q * 4 + 0] = __float2half_rn(__expf(LOG16 - f.x * inv_eps));
            dst[q * 4 + 1] = __float2half_rn(__expf(LOG16 - f.y * inv_eps));
            dst[q * 4 + 2] = __float2half_rn(__expf(LOG16 - f.z * inv_eps));
            dst[q * 4 + 3] = __float2half_rn(__expf(LOG16 - f.w * inv_eps));
        }
    }
    __syncthreads();

    const int warp = tid >> 5, lane = tid & 31;
    const int rr = lane >> 2, cc = (lane & 3) << 1;

#pragma unroll
    for (int p = 0; p < 2; ++p) {
        const int t = warp * 2 + p;          // 0..15
        const int i = t >> 2, j = t & 3;

        {   // K tile: rows = C rows, k = C cols
            const __half* b = sE + (i * 16 + rr) * 72 + (j * 16 + cc);
            unsigned r0 = *(const unsigned*)(b);
            unsigned r1 = *(const unsigned*)(b + 8 * 72);
            unsigned r2 = *(const unsigned*)(b + 8);
            unsigned r3 = *(const unsigned*)(b + 8 * 72 + 8);
            size_t tileK = ((size_t)((by >> 4) + i) * NTILES) + (bx >> 4) + j;
            ((uint4*)g_K)[tileK * 32 + lane] = make_uint4(r0, r1, r2, r3);
        }
        {   // KT tile: rows = C cols, k = C rows (transposed read)
            const __half* b = sE + (j * 16 + cc) * 72 + (i * 16 + rr);
            unsigned r0 = packh(b[0],          b[72]);
            unsigned r1 = packh(b[8],          b[72 + 8]);
            unsigned r2 = packh(b[8 * 72],     b[9 * 72]);
            unsigned r3 = packh(b[8 * 72 + 8], b[9 * 72 + 8]);
            size_t tileT = ((size_t)((bx >> 4) + i) * NTILES) + (by >> 4) + j;
            ((uint4*)g_KT)[tileT * 32 + lane] = make_uint4(r0, r1, r2, r3);
        }
    }
}

// ---------------------------------------------------------------------------
// Persistent tensor-core Sinkhorn (R14 mainloop, per-GROUP dataflow sync)
// with finalize FUSED into the last two epilogues (no g_pu/g_pv, no final
// barrier). 256 blocks x 256 threads. Block rt = 16 rows x FULL 4096 cols;
// warp w covers k-tiles [32w, 32w+32) = B tiles produced by group w.
// ---------------------------------------------------------------------------
__global__ void __launch_bounds__(NTHREADS, 2)
sinkhorn_persistent_kernel(const float* __restrict__ alpha,
                           const float* __restrict__ beta,
                           const float* __restrict__ epsp,
                           float* __restrict__ out) {
    __shared__ float    red[8 * 16 * 4];
    __shared__ __half   yb[16 * 4];
    __shared__ unsigned sbase[8];

    const int tid  = threadIdx.x;
    const int warp = tid >> 5;
    const int lane = tid & 31;
    const int rt   = blockIdx.x;
    const int row0 = rt * 16;
    const bool bl  = lane < 16;
    const float eps = *epsp;

    const unsigned* mycnt  = g_gc + warp * 32;      // group this warp consumes
    unsigned*       arrcnt = g_gc + (rt >> 5) * 32; // group this block produces

    // read launch-base counter values BEFORE any arrival, then fence grid-wide
    if (tid < 8) {
        unsigned c;
        asm volatile("ld.relaxed.gpu.b32 %0, [%1];" : "=r"(c) : "l"(g_gc + tid * 32));
        sbase[tid] = c;
    }
    grid_sync();   // all base reads done; packer output visible

    const unsigned base = sbase[warp];

    // init packed v = 1.0 (tile rt), publish as generation 1
    if (warp == 0 && bl)
        __stcg(&g_Bv[rt * 16 + lane], make_uint2(0x3C003C00u, 0x3C003C00u));
    __syncthreads();
    if (tid == 0) {
        unsigned dummy;
        asm volatile("atom.add.release.gpu.u32 %0, [%1], 1;"
                     : "=r"(dummy) : "l"(arrcnt) : "memory");
    }

    const size_t fbase = ((size_t)rt * NTILES + warp * TPW) * 32 + lane;

    for (int it = 0; it < 2 * NITER; ++it) {
        const __half* M    = (it & 1) ? g_KT : g_K;
        const uint2*  Bin  = (it & 1) ? g_Bu : g_Bv;
        uint2*        Bout = (it & 1) ? g_Bv : g_Bu;
        const float*  num  = (it & 1) ? beta : alpha;

        const uint4* kf = (const uint4*)M + fbase;
        const uint2* bf = Bin + (warp * TPW) * 16 + lane;

        float dA0 = 0.f, dA1 = 0.f, dA2 = 0.f, dA3 = 0.f;
        float dB0 = 0.f, dB1 = 0.f, dB2 = 0.f, dB3 = 0.f;

        uint4 ka[4];
        uint2 ba[4];
        // K prologue loads do NOT depend on producers: issue before the wait
#pragma unroll
        for (int q = 0; q < 4; ++q) ka[q] = __ldcg(kf + q * 32);

        // dataflow wait: group w must have published generation it+1
        wait_group(mycnt, base + (unsigned)(it + 1) * 32);

#pragma unroll
        for (int q = 0; q < 4; ++q)
            ba[q] = bl ? __ldcg(bf + q * 16) : make_uint2(0u, 0u);

#pragma unroll
        for (int g = 0; g < TPW / 4; ++g) {      // 8 groups of 4 tiles
            uint4 nk[4];
            uint2 nb[4];
#pragma unroll
            for (int q = 0; q < 4; ++q) {
                if (g < TPW / 4 - 1) {
                    nk[q] = __ldcg(kf + ((g + 1) * 4 + q) * 32);
                    nb[q] = bl ? __ldcg(bf + ((g + 1) * 4 + q) * 16) : make_uint2(0u, 0u);
                } else { nk[q] = ka[q]; nb[q] = ba[q]; }
            }
#pragma unroll
            for (int q = 0; q < 4; ++q) {
                if (q & 1) {
                    asm volatile("mma.sync.aligned.m16n8k16.row.col.f32.f16.f16.f32 "
                                 "{%0,%1,%2,%3}, {%4,%5,%6,%7}, {%8,%9}, {%0,%1,%2,%3};"
                                 : "+f"(dB0), "+f"(dB1), "+f"(dB2), "+f"(dB3)
                                 : "r"(ka[q].x), "r"(ka[q].y), "r"(ka[q].z), "r"(ka[q].w),
                                   "r"(ba[q].x), "r"(ba[q].y));
                } else {
                    asm volatile("mma.sync.aligned.m16n8k16.row.col.f32.f16.f16.f32 "
                                 "{%0,%1,%2,%3}, {%4,%5,%6,%7}, {%8,%9}, {%0,%1,%2,%3};"
                                 : "+f"(dA0), "+f"(dA1), "+f"(dA2), "+f"(dA3)
                                 : "r"(ka[q].x), "r"(ka[q].y), "r"(ka[q].z), "r"(ka[q].w),
                                   "r"(ba[q].x), "r"(ba[q].y));
                }
            }
#pragma unroll
            for (int q = 0; q < 4; ++q) { ka[q] = nk[q]; ba[q] = nb[q]; }
        }

        const float d0 = dA0 + dB0, d1 = dA1 + dB1;
        const float d2 = dA2 + dB2, d3 = dA3 + dB3;

        // ---- epilogue: C fragments (cols 0-3 useful) -> smem -> reduce ----
        if ((lane & 3) < 2) {
            const int c = 2 * (lane & 3);
            const int r = lane >> 2;
            red[(warp * 16 + r) * 4 + c]         = d0;
            red[(warp * 16 + r) * 4 + c + 1]     = d1;
            red[(warp * 16 + r + 8) * 4 + c]     = d2;
            red[(warp * 16 + r + 8) * 4 + c + 1] = d3;
        }
        __syncthreads();
        if (tid < 64) {
            const int row = tid >> 2, c = tid & 3;
            float p = 0.f;
#pragma unroll
            for (int w = 0; w < 8; ++w)
                p += red[(w * 16 + row) * 4 + c];
            float a = __ldg(num + (size_t)c * N + row0 + row);
            float y = __fdividef(F_SCALE * a, p);
            yb[row * 4 + c] = __float2half_rn(y);
            // FUSED finalize: last even pass -> f, last odd pass -> g
            if (it >= 2 * NITER - 2) {
                float* o = out + ((it & 1) ? 4 * N : 0);
                const float corr = (it & 1) ? LOG_CU : LOG16;
                o[(size_t)c * N + row0 + row] = eps * (logf(a) - logf(p) + corr);
            }
        }
        __syncthreads();
        // pack tile rt of the next B operand (lanes 0-15; n>=4 implicit zero)
        if (warp == 0 && bl) {
            const int n = lane >> 2, k0 = (lane & 3) * 2;
            uint2 o;
            o.x = packh(yb[k0 * 4 + n],       yb[(k0 + 1) * 4 + n]);
            o.y = packh(yb[(k0 + 8) * 4 + n], yb[(k0 + 9) * 4 + n]);
            __stcg(&Bout[rt * 16 + lane], o);
        }
        __syncthreads();   // pack visible block-wide before publish
        if (tid == 0) {
            unsigned dummy;
            asm volatile("atom.add.release.gpu.u32 %0, [%1], 1;"
                         : "=r"(dummy) : "l"(arrcnt) : "memory");
        }
    }
    // no finalize, no final barrier: all of `out` was written by the
    // fused epilogues of passes 18 (f) and 19 (g).
}

// ---------------------------------------------------------------------------
extern "C" void kernel_launch(void* const* d_in, const int* in_sizes, int n_in,
                              void* d_out, int out_size) {
    const float* alpha = (const float*)d_in[0];
    const float* beta  = (const float*)d_in[1];
    const float* C     = (const float*)d_in[2];
    const float* eps   = (const float*)d_in[3];
    float* out = (float*)d_out;

    frag_pack_kernel<<<dim3(64, 64), 256>>>(C, eps);
    sinkhorn_persistent_kernel<<<NBLOCKS, NTHREADS>>>(alpha, beta, eps, out);
}